// round 1
// baseline (speedup 1.0000x reference)
#include <cuda_runtime.h>
#include <math.h>

#define L_SEQ 2048
#define BATCH 2
#define EMB   256
#define NH    8
#define HD    32
#define MROWS (L_SEQ*BATCH)          // 4096
#define ATT_SCALE 0.17677669529663687f  // HD^-0.5

// Scratch (allocation-free rule: __device__ globals)
__device__ float g_Q[MROWS*EMB];
__device__ float g_K[MROWS*EMB];
__device__ float g_V[MROWS*EMB];
__device__ float g_O[MROWS*EMB];

// ---------------------------------------------------------------------------
// GEMM: out = X[M,256] @ W[256,256] + bias.   M=4096.
// MODE 0: out[m*256+n]   (plain row-major, used for final projection)
// MODE 1: out[((b*NH+h)*L + l)*HD + d]  with m=l*B+b, n=h*HD+d  (per-head QKV)
// Tiling: BM=BN=64, BK=16, 256 threads, 4x4 microtile, float4 paths.
// ---------------------------------------------------------------------------
template<int MODE>
__global__ __launch_bounds__(256) void gemm_kernel(
    const float* __restrict__ X, const float* __restrict__ W,
    const float* __restrict__ bias, float* __restrict__ out)
{
    const int BM = 64, BN = 64, BK = 16;
    __shared__ float As[BK][BM];
    __shared__ float Bs[BK][BN];

    const int tid = threadIdx.x;
    const int tx = tid & 15;       // 0..15 -> 4 cols each
    const int ty = tid >> 4;       // 0..15 -> 4 rows each
    const int bm = blockIdx.y * BM;
    const int bn = blockIdx.x * BN;

    const int arow  = tid >> 2;    // 0..63
    const int acol4 = tid & 3;     // 0..3  (float4 slot inside BK=16)
    const int brow  = tid >> 4;    // 0..15
    const int bcol4 = tid & 15;    // 0..15 (float4 slot inside BN=64)

    float acc[4][4] = {};

    for (int kt = 0; kt < EMB; kt += BK) {
        float4 av = *(const float4*)&X[(bm + arow)*EMB + kt + acol4*4];
        As[acol4*4+0][arow] = av.x;
        As[acol4*4+1][arow] = av.y;
        As[acol4*4+2][arow] = av.z;
        As[acol4*4+3][arow] = av.w;
        float4 bv = *(const float4*)&W[(kt + brow)*EMB + bn + bcol4*4];
        *(float4*)&Bs[brow][bcol4*4] = bv;
        __syncthreads();

        #pragma unroll
        for (int kk = 0; kk < BK; kk++) {
            float4 a = *(const float4*)&As[kk][ty*4];
            float4 b = *(const float4*)&Bs[kk][tx*4];
            float ar[4] = {a.x, a.y, a.z, a.w};
            float br[4] = {b.x, b.y, b.z, b.w};
            #pragma unroll
            for (int i = 0; i < 4; i++)
                #pragma unroll
                for (int j = 0; j < 4; j++)
                    acc[i][j] += ar[i] * br[j];
        }
        __syncthreads();
    }

    #pragma unroll
    for (int i = 0; i < 4; i++) {
        const int m = bm + ty*4 + i;
        #pragma unroll
        for (int j = 0; j < 4; j++) {
            const int n = bn + tx*4 + j;
            const float v = acc[i][j] + bias[n];
            if (MODE == 0) {
                out[m*EMB + n] = v;
            } else {
                const int b = m & (BATCH-1);   // m % 2
                const int l = m >> 1;          // m / 2
                const int h = n >> 5;          // n / HD
                const int d = n & (HD-1);
                out[((b*NH + h)*L_SEQ + l)*HD + d] = v;
            }
        }
    }
}

// ---------------------------------------------------------------------------
// Flash attention, fp32, online softmax.
// grid: (L/64, B*NH), block: 64 threads. One thread owns one query row:
// q[32], o[32], s[64] register-resident (all inner loops fully unrolled).
// K/V 64x32 tiles staged in smem; score reads are warp-broadcast LDS.128.
// ---------------------------------------------------------------------------
__global__ __launch_bounds__(64) void flash_kernel(float* __restrict__ Oout)
{
    const int Br = 64, Bc = 64;
    __shared__ float4 Ks[Bc][HD/4];
    __shared__ float4 Vs[Bc][HD/4];

    const int t  = threadIdx.x;
    const int bh = blockIdx.y;               // b*NH + h
    const int r  = blockIdx.x * Br + t;      // query row (0..L-1)

    // load q into registers
    const float4* qptr = (const float4*)(g_Q + (bh*L_SEQ + r)*HD);
    float q[HD];
    #pragma unroll
    for (int d4 = 0; d4 < HD/4; d4++) {
        float4 v = qptr[d4];
        q[d4*4+0] = v.x; q[d4*4+1] = v.y; q[d4*4+2] = v.z; q[d4*4+3] = v.w;
    }

    float o[HD] = {};
    float mrun = -1e30f;
    float lsum = 0.f;

    const float4* Kg = (const float4*)(g_K + bh*L_SEQ*HD);
    const float4* Vg = (const float4*)(g_V + bh*L_SEQ*HD);

    for (int kt = 0; kt < L_SEQ/Bc; kt++) {
        // cooperative tile load: 512 float4 per tile, 8 per thread
        #pragma unroll
        for (int i = 0; i < 8; i++) {
            const int idx = t + i*64;
            ((float4*)Ks)[idx] = Kg[kt*Bc*(HD/4) + idx];
            ((float4*)Vs)[idx] = Vg[kt*Bc*(HD/4) + idx];
        }
        __syncthreads();

        // scores for this tile (fully unrolled -> s[] stays in registers)
        float s[Bc];
        float mt = -1e30f;
        #pragma unroll
        for (int j = 0; j < Bc; j++) {
            float acc = 0.f;
            #pragma unroll
            for (int d4 = 0; d4 < HD/4; d4++) {
                float4 kv = Ks[j][d4];           // warp broadcast
                acc += q[d4*4+0]*kv.x + q[d4*4+1]*kv.y
                     + q[d4*4+2]*kv.z + q[d4*4+3]*kv.w;
            }
            s[j] = acc * ATT_SCALE;
            mt = fmaxf(mt, s[j]);
        }

        // online softmax update
        const float mnew = fmaxf(mrun, mt);
        const float corr = __expf(mrun - mnew);
        lsum *= corr;
        #pragma unroll
        for (int d = 0; d < HD; d++) o[d] *= corr;

        #pragma unroll
        for (int j = 0; j < Bc; j++) {
            const float p = __expf(s[j] - mnew);
            lsum += p;
            #pragma unroll
            for (int d4 = 0; d4 < HD/4; d4++) {
                float4 vv = Vs[j][d4];           // warp broadcast
                o[d4*4+0] += p*vv.x; o[d4*4+1] += p*vv.y;
                o[d4*4+2] += p*vv.z; o[d4*4+3] += p*vv.w;
            }
        }
        mrun = mnew;
        __syncthreads();
    }

    // normalize + store to [m = l*B+b, e = h*HD+d] layout for the final GEMM
    const float inv = 1.f / lsum;
    const int b = bh >> 3;     // / NH
    const int h = bh & (NH-1);
    float* optr = Oout + (r*BATCH + b)*EMB + h*HD;
    #pragma unroll
    for (int d4 = 0; d4 < HD/4; d4++) {
        float4 v;
        v.x = o[d4*4+0]*inv; v.y = o[d4*4+1]*inv;
        v.z = o[d4*4+2]*inv; v.w = o[d4*4+3]*inv;
        *(float4*)&optr[d4*4] = v;
    }
}

// ---------------------------------------------------------------------------
extern "C" void kernel_launch(void* const* d_in, const int* in_sizes, int n_in,
                              void* d_out, int out_size)
{
    (void)in_sizes; (void)n_in; (void)out_size;
    const float* query = (const float*)d_in[0];
    const float* key_  = (const float*)d_in[1];
    const float* value = (const float*)d_in[2];
    const float* Wq    = (const float*)d_in[3];
    const float* bq    = (const float*)d_in[4];
    const float* Wk    = (const float*)d_in[5];
    const float* bk    = (const float*)d_in[6];
    const float* Wv    = (const float*)d_in[7];
    const float* bv    = (const float*)d_in[8];
    const float* Wp    = (const float*)d_in[9];
    const float* bp    = (const float*)d_in[10];
    float* out = (float*)d_out;

    float *Qp, *Kp, *Vp, *Op;
    cudaGetSymbolAddress((void**)&Qp, g_Q);
    cudaGetSymbolAddress((void**)&Kp, g_K);
    cudaGetSymbolAddress((void**)&Vp, g_V);
    cudaGetSymbolAddress((void**)&Op, g_O);

    dim3 ggrid(EMB/64, MROWS/64);   // (4, 64)
    gemm_kernel<1><<<ggrid, 256>>>(query, Wq, bq, Qp);
    gemm_kernel<1><<<ggrid, 256>>>(key_,  Wk, bk, Kp);
    gemm_kernel<1><<<ggrid, 256>>>(value, Wv, bv, Vp);

    dim3 fgrid(L_SEQ/64, BATCH*NH); // (32, 16)
    flash_kernel<<<fgrid, 64>>>(Op);

    gemm_kernel<0><<<ggrid, 256>>>(Op, Wp, bp, out);
}